// round 10
// baseline (speedup 1.0000x reference)
#include <cuda_runtime.h>
#include <cuda_bf16.h>
#include <cstdint>

#define N_USER 50000
#define N_ITEM 100000
#define N_TOT  150000
#define D      64
#define NNZ    2400000
#define B_SZ   4096
#define N_LAYERS 3

#define SCAN_B 1024
#define SCAN_NBLK ((N_TOT + SCAN_B - 1) / SCAN_B)   // 147

#define GROWS 32                                    // gemm rows/block
#define GBLK ((N_TOT + GROWS - 1) / GROWS)          // 4688

#define SAP  136   // A-plane k-stride (bf16): bank-free frag loads

// ---------------- device scratch (allocation-free rule) ----------------
__device__ float g_E0[N_TOT * D];
__device__ float g_E1[N_TOT * D];
__device__ float g_A[N_TOT * 128];        // A' = [L+E | L*E] per row
__device__ float g_all[N_TOT * 4 * D];
__device__ int   g_cnt[N_TOT];
__device__ int   g_rowptr[N_TOT + 1];
__device__ int   g_cur[N_TOT];
__device__ int   g_bsum[SCAN_NBLK + 1];
__device__ int2  g_csr[NNZ];
__device__ __nv_bfloat16 g_Whi[N_LAYERS][64 * 128];  // [n][k], W'=[Wgc;Wbi]
__device__ __nv_bfloat16 g_Wlo[N_LAYERS][64 * 128];

// ---------------------------------------------------------------------------
__global__ void init_kernel(const float* __restrict__ user_emb,
                            const float* __restrict__ item_emb) {
    int i = blockIdx.x * blockDim.x + threadIdx.x;
    if (i >= N_TOT * D) return;
    float v = (i < N_USER * D) ? user_emb[i] : item_emb[i - N_USER * D];
    g_E0[i] = v;
    int row = i >> 6, col = i & 63;
    g_all[row * (4 * D) + col] = v;
    if (col == 0) g_cnt[row] = 0;
}

// W' -> bf16 hi/lo planes, [n][k] layout. One block per layer.
__global__ void wconv_kernel(const float* __restrict__ Wgc,
                             const float* __restrict__ Wbi) {
    int layer = blockIdx.x;
    const float* wg = Wgc + layer * 4096;
    const float* wb = Wbi + layer * 4096;
    for (int idx = threadIdx.x; idx < 64 * 128; idx += blockDim.x) {
        int n = idx >> 7, k = idx & 127;
        float w = (k < 64) ? wg[k * 64 + n] : wb[(k - 64) * 64 + n];
        __nv_bfloat16 h = __float2bfloat16(w);
        g_Whi[layer][idx] = h;
        g_Wlo[layer][idx] = __float2bfloat16(w - __bfloat162float(h));
    }
}

// ---------------------------------------------------------------------------
// CSR build
// ---------------------------------------------------------------------------
__global__ void hist_kernel(const int* __restrict__ rows) {
    int i = blockIdx.x * blockDim.x + threadIdx.x;
    if (i < NNZ) atomicAdd(&g_cnt[rows[i]], 1);
}

__global__ void scan1_kernel() {
    __shared__ int s[SCAN_B];
    int tid = threadIdx.x;
    int gid = blockIdx.x * SCAN_B + tid;
    int v = (gid < N_TOT) ? g_cnt[gid] : 0;
    s[tid] = v;
    __syncthreads();
    #pragma unroll
    for (int off = 1; off < SCAN_B; off <<= 1) {
        int t = (tid >= off) ? s[tid - off] : 0;
        __syncthreads();
        s[tid] += t;
        __syncthreads();
    }
    if (gid < N_TOT) g_rowptr[gid] = s[tid] - v;
    if (tid == SCAN_B - 1) g_bsum[blockIdx.x] = s[tid];
}

__global__ void scan2_kernel() {
    __shared__ int s[256];
    int tid = threadIdx.x;
    int v = (tid < SCAN_NBLK) ? g_bsum[tid] : 0;
    s[tid] = v;
    __syncthreads();
    #pragma unroll
    for (int off = 1; off < 256; off <<= 1) {
        int t = (tid >= off) ? s[tid - off] : 0;
        __syncthreads();
        s[tid] += t;
        __syncthreads();
    }
    if (tid < SCAN_NBLK) g_bsum[tid] = s[tid] - v;
}

__global__ void scan3_kernel() {
    int gid = blockIdx.x * SCAN_B + threadIdx.x;
    if (gid < N_TOT) {
        g_rowptr[gid] += g_bsum[blockIdx.x];
        g_cur[gid] = 0;
    }
    if (gid == 0) g_rowptr[N_TOT] = NNZ;
}

__global__ void scatter_kernel(const float* __restrict__ vals,
                               const int*   __restrict__ rows,
                               const int*   __restrict__ cols) {
    int i = blockIdx.x * blockDim.x + threadIdx.x;
    if (i >= NNZ) return;
    int r = rows[i];
    int pos = g_rowptr[r] + atomicAdd(&g_cur[r], 1);
    g_csr[pos] = make_int2(cols[i], __float_as_int(vals[i]));
}

// ---------------------------------------------------------------------------
// Lean CSR SPMM: 16 threads/row, register accumulation, writes
// A' = [L+E | L*E] fp32 to g_A. No smem, low regs -> max occupancy.
// ---------------------------------------------------------------------------
__global__ void __launch_bounds__(256)
spmm_kernel(const float* __restrict__ ego_in) {
    int tid = threadIdx.x;
    int row = blockIdx.x * 16 + (tid >> 4);     // grid = N_TOT/16 exactly
    int c   = (tid & 15) << 2;
    int s0 = g_rowptr[row];
    int e0 = g_rowptr[row + 1];
    float4 acc0 = make_float4(0.f, 0.f, 0.f, 0.f);
    float4 acc1 = make_float4(0.f, 0.f, 0.f, 0.f);
    int j = s0;
    for (; j + 4 <= e0; j += 4) {
        int2 a  = __ldg(&g_csr[j]);
        int2 b  = __ldg(&g_csr[j + 1]);
        int2 cc = __ldg(&g_csr[j + 2]);
        int2 dd = __ldg(&g_csr[j + 3]);
        float4 va = __ldg((const float4*)&ego_in[a.x * D + c]);
        float4 vb = __ldg((const float4*)&ego_in[b.x * D + c]);
        float4 vc = __ldg((const float4*)&ego_in[cc.x * D + c]);
        float4 vd = __ldg((const float4*)&ego_in[dd.x * D + c]);
        float fa = __int_as_float(a.y);
        float fb = __int_as_float(b.y);
        float fc = __int_as_float(cc.y);
        float fd = __int_as_float(dd.y);
        acc0.x += fa * va.x + fb * vb.x;
        acc0.y += fa * va.y + fb * vb.y;
        acc0.z += fa * va.z + fb * vb.z;
        acc0.w += fa * va.w + fb * vb.w;
        acc1.x += fc * vc.x + fd * vd.x;
        acc1.y += fc * vc.y + fd * vd.y;
        acc1.z += fc * vc.z + fd * vd.z;
        acc1.w += fc * vc.w + fd * vd.w;
    }
    for (; j < e0; j++) {
        int2 a = __ldg(&g_csr[j]);
        float4 va = __ldg((const float4*)&ego_in[a.x * D + c]);
        float fa = __int_as_float(a.y);
        acc0.x += fa * va.x; acc0.y += fa * va.y;
        acc0.z += fa * va.z; acc0.w += fa * va.w;
    }
    float4 acc = make_float4(acc0.x + acc1.x, acc0.y + acc1.y,
                             acc0.z + acc1.z, acc0.w + acc1.w);
    float4 e = *(const float4*)&ego_in[row * D + c];
    float4 li = make_float4(acc.x + e.x, acc.y + e.y, acc.z + e.z, acc.w + e.w);
    float4 bi = make_float4(acc.x * e.x, acc.y * e.y, acc.z * e.z, acc.w * e.w);
    *(float4*)&g_A[row * 128 + c]      = li;
    *(float4*)&g_A[row * 128 + 64 + c] = bi;
}

// ---------------------------------------------------------------------------
#define MMA_BF16(C, A0, A1, A2, A3, B0, B1)                                   \
    asm volatile(                                                             \
        "mma.sync.aligned.m16n8k16.row.col.f32.bf16.bf16.f32 "                \
        "{%0,%1,%2,%3}, {%4,%5,%6,%7}, {%8,%9}, {%0,%1,%2,%3};"               \
        : "+f"(C[0]), "+f"(C[1]), "+f"(C[2]), "+f"(C[3])                      \
        : "r"(A0), "r"(A1), "r"(A2), "r"(A3), "r"(B0), "r"(B1))

__device__ __forceinline__ uint32_t pack_hi(float a, float b) {
    __nv_bfloat162 h = __floats2bfloat162_rn(a, b);
    return *reinterpret_cast<uint32_t*>(&h);
}

// ---------------------------------------------------------------------------
// Streaming GEMM layer kernel (32 rows/block):
//   Stage: read A' tile fp32 coalesced, split to bf16 hi/lo smem planes.
//   MMA:   3-product split-bf16 mma.sync; B frags via __ldg (L1-hot).
//   Epi:   +2b, leaky-relu, row-norm, write ego_out and g_all slab.
// ---------------------------------------------------------------------------
__global__ void __launch_bounds__(256)
gemm_layer_kernel(float* __restrict__ ego_out,
                  const __nv_bfloat16* __restrict__ Whi,
                  const __nv_bfloat16* __restrict__ Wlo,
                  const float* __restrict__ bb,
                  int layer) {
    __shared__ __nv_bfloat16 sAhi[GROWS * SAP];
    __shared__ __nv_bfloat16 sAlo[GROWS * SAP];
    __shared__ float sC[GROWS * 64];

    int tid = threadIdx.x;
    int rowBase = blockIdx.x * GROWS;

    // ---- stage + split A' tile: 1024 float4, 4 per thread ----
    {
        #pragma unroll
        for (int p = 0; p < 4; p++) {
            int i4 = p * 256 + tid;
            int rl = i4 >> 5;                 // local row
            int c  = (i4 & 31) * 4;           // k offset
            int grow = rowBase + rl;
            float4 a = (grow < N_TOT)
                ? *(const float4*)&g_A[grow * 128 + c]
                : make_float4(0.f, 0.f, 0.f, 0.f);
            uint32_t h0 = pack_hi(a.x, a.y);
            uint32_t h1 = pack_hi(a.z, a.w);
            __nv_bfloat162 hh0 = *reinterpret_cast<__nv_bfloat162*>(&h0);
            __nv_bfloat162 hh1 = *reinterpret_cast<__nv_bfloat162*>(&h1);
            uint32_t l0 = pack_hi(a.x - __bfloat162float(hh0.x),
                                  a.y - __bfloat162float(hh0.y));
            uint32_t l1 = pack_hi(a.z - __bfloat162float(hh1.x),
                                  a.w - __bfloat162float(hh1.y));
            *(uint2*)&sAhi[rl * SAP + c] = make_uint2(h0, h1);
            *(uint2*)&sAlo[rl * SAP + c] = make_uint2(l0, l1);
        }
    }
    __syncthreads();

    // ---- MMA: warp wid -> m-tile wid>>2, n-tile pair (wid&3)*2 ----
    int wid = tid >> 5, lane = tid & 31;
    int gid = lane >> 2, tig = lane & 3;
    int m = wid >> 2;
    int nt0 = (wid & 3) * 2;

    float C0[4] = {0.f, 0.f, 0.f, 0.f};
    float C1[4] = {0.f, 0.f, 0.f, 0.f};

    int arow = m * 16 + gid;
    #pragma unroll
    for (int ks = 0; ks < 8; ks++) {
        int k0 = ks * 16 + 2 * tig;
        uint32_t ah0 = *(const uint32_t*)&sAhi[arow * SAP + k0];
        uint32_t ah1 = *(const uint32_t*)&sAhi[(arow + 8) * SAP + k0];
        uint32_t ah2 = *(const uint32_t*)&sAhi[arow * SAP + k0 + 8];
        uint32_t ah3 = *(const uint32_t*)&sAhi[(arow + 8) * SAP + k0 + 8];
        uint32_t al0 = *(const uint32_t*)&sAlo[arow * SAP + k0];
        uint32_t al1 = *(const uint32_t*)&sAlo[(arow + 8) * SAP + k0];
        uint32_t al2 = *(const uint32_t*)&sAlo[arow * SAP + k0 + 8];
        uint32_t al3 = *(const uint32_t*)&sAlo[(arow + 8) * SAP + k0 + 8];

        #pragma unroll
        for (int t = 0; t < 2; t++) {
            int n = (nt0 + t) * 8 + gid;
            const __nv_bfloat16* bph = &Whi[n * 128 + k0];
            const __nv_bfloat16* bpl = &Wlo[n * 128 + k0];
            uint32_t bh0 = __ldg((const uint32_t*)bph);
            uint32_t bh1 = __ldg((const uint32_t*)(bph + 8));
            uint32_t bl0 = __ldg((const uint32_t*)bpl);
            uint32_t bl1 = __ldg((const uint32_t*)(bpl + 8));
            float* C = (t == 0) ? C0 : C1;
            MMA_BF16(C, ah0, ah1, ah2, ah3, bh0, bh1);   // hi*hi
            MMA_BF16(C, ah0, ah1, ah2, ah3, bl0, bl1);   // hi*lo
            MMA_BF16(C, al0, al1, al2, al3, bh0, bh1);   // lo*hi
        }
    }

    {
        int r = m * 16 + gid;
        #pragma unroll
        for (int t = 0; t < 2; t++) {
            const float* C = (t == 0) ? C0 : C1;
            int cb = (nt0 + t) * 8 + tig * 2;
            *(float2*)&sC[r * 64 + cb]       = make_float2(C[0], C[1]);
            *(float2*)&sC[(r + 8) * 64 + cb] = make_float2(C[2], C[3]);
        }
    }
    __syncthreads();

    // ---- epilogue: 2 rows x 4 cols per thread ----
    {
        int ty = tid >> 4;
        int tx = tid & 15;
        float4 b4 = *(const float4*)&bb[4 * tx];
        float4 X = *(const float4*)&sC[(2 * ty) * 64 + 4 * tx];
        float4 Y = *(const float4*)&sC[(2 * ty + 1) * 64 + 4 * tx];

        // reference adds b_bi to BOTH branches -> 2*b
        float x0 = X.x + 2.f * b4.x, x1 = X.y + 2.f * b4.y;
        float x2 = X.z + 2.f * b4.z, x3 = X.w + 2.f * b4.w;
        float y0 = Y.x + 2.f * b4.x, y1 = Y.y + 2.f * b4.y;
        float y2 = Y.z + 2.f * b4.z, y3 = Y.w + 2.f * b4.w;

        x0 = x0 > 0.f ? x0 : 0.01f * x0;  x1 = x1 > 0.f ? x1 : 0.01f * x1;
        x2 = x2 > 0.f ? x2 : 0.01f * x2;  x3 = x3 > 0.f ? x3 : 0.01f * x3;
        y0 = y0 > 0.f ? y0 : 0.01f * y0;  y1 = y1 > 0.f ? y1 : 0.01f * y1;
        y2 = y2 > 0.f ? y2 : 0.01f * y2;  y3 = y3 > 0.f ? y3 : 0.01f * y3;

        float ss0 = x0 * x0 + x1 * x1 + x2 * x2 + x3 * x3;
        float ss1 = y0 * y0 + y1 * y1 + y2 * y2 + y3 * y3;
        #pragma unroll
        for (int o = 8; o; o >>= 1) {
            ss0 += __shfl_xor_sync(0xffffffffu, ss0, o);
            ss1 += __shfl_xor_sync(0xffffffffu, ss1, o);
        }
        float inv0 = 1.0f / fmaxf(sqrtf(ss0), 1e-12f);
        float inv1 = 1.0f / fmaxf(sqrtf(ss1), 1e-12f);

        int r0 = rowBase + 2 * ty;
        int r1 = r0 + 1;
        int co = (layer + 1) * D + 4 * tx;
        if (r0 < N_TOT) {
            *(float4*)&ego_out[r0 * D + 4 * tx] = make_float4(x0, x1, x2, x3);
            *(float4*)&g_all[r0 * (4 * D) + co] =
                make_float4(x0 * inv0, x1 * inv0, x2 * inv0, x3 * inv0);
        }
        if (r1 < N_TOT) {
            *(float4*)&ego_out[r1 * D + 4 * tx] = make_float4(y0, y1, y2, y3);
            *(float4*)&g_all[r1 * (4 * D) + co] =
                make_float4(y0 * inv1, y1 * inv1, y2 * inv1, y3 * inv1);
        }
    }
}

// ---------------------------------------------------------------------------
__global__ void gather_kernel(const int* __restrict__ users,
                              const int* __restrict__ pos_items,
                              const int* __restrict__ neg_items,
                              float* __restrict__ out) {
    int idx = blockIdx.x * blockDim.x + threadIdx.x;  // 3*B*256
    if (idx >= 3 * B_SZ * (4 * D)) return;
    int which = idx / (B_SZ * 4 * D);
    int rem   = idx - which * (B_SZ * 4 * D);
    int b = rem >> 8;
    int c = rem & 255;
    int row;
    if (which == 0)      row = users[b];
    else if (which == 1) row = N_USER + pos_items[b];
    else                 row = N_USER + neg_items[b];
    out[idx] = g_all[row * (4 * D) + c];
}

// ---------------------------------------------------------------------------
extern "C" void kernel_launch(void* const* d_in, const int* in_sizes, int n_in,
                              void* d_out, int out_size) {
    const float* user_emb  = (const float*)d_in[0];
    const float* item_emb  = (const float*)d_in[1];
    const float* W_gc      = (const float*)d_in[2];
    const float* W_bi      = (const float*)d_in[3];
    const float* b_bi      = (const float*)d_in[4];
    const float* vals      = (const float*)d_in[5];
    const int*   rows      = (const int*)d_in[6];
    const int*   cols      = (const int*)d_in[7];
    const int*   users     = (const int*)d_in[8];
    const int*   pos_items = (const int*)d_in[9];
    const int*   neg_items = (const int*)d_in[10];
    float* out = (float*)d_out;

    init_kernel<<<(N_TOT * D + 255) / 256, 256>>>(user_emb, item_emb);
    wconv_kernel<<<N_LAYERS, 256>>>(W_gc, W_bi);

    hist_kernel<<<(NNZ + 255) / 256, 256>>>(rows);
    scan1_kernel<<<SCAN_NBLK, SCAN_B>>>();
    scan2_kernel<<<1, 256>>>();
    scan3_kernel<<<SCAN_NBLK, SCAN_B>>>();
    scatter_kernel<<<(NNZ + 255) / 256, 256>>>(vals, rows, cols);

    float* e0; float* e1;
    cudaGetSymbolAddress((void**)&e0, g_E0);
    cudaGetSymbolAddress((void**)&e1, g_E1);
    __nv_bfloat16* whi; __nv_bfloat16* wlo;
    cudaGetSymbolAddress((void**)&whi, g_Whi);
    cudaGetSymbolAddress((void**)&wlo, g_Wlo);

    for (int k = 0; k < N_LAYERS; k++) {
        const float* in   = (k & 1) ? e1 : e0;
        float*       outp = (k & 1) ? e0 : e1;
        spmm_kernel<<<N_TOT / 16, 256>>>(in);
        gemm_layer_kernel<<<GBLK, 256>>>(outp,
                                         whi + k * 64 * 128,
                                         wlo + k * 64 * 128,
                                         b_bi + k * D, k);
    }

    gather_kernel<<<(3 * B_SZ * 4 * D + 255) / 256, 256>>>(users, pos_items,
                                                           neg_items, out);
}

// round 11
// speedup vs baseline: 1.5172x; 1.5172x over previous
#include <cuda_runtime.h>
#include <cuda_bf16.h>
#include <cstdint>

#define N_USER 50000
#define N_ITEM 100000
#define N_TOT  150000
#define D      64
#define NNZ    2400000
#define B_SZ   4096
#define N_LAYERS 3

#define SCAN_B 1024
#define SCAN_NBLK ((N_TOT + SCAN_B - 1) / SCAN_B)   // 147

#define ROWS_PER_BLK 32
#define LBLK ((N_TOT + ROWS_PER_BLK - 1) / ROWS_PER_BLK)  // 4688

#define SAP  136   // A-plane k-stride (bf16): bank-free frag loads

// ---------------- device scratch (allocation-free rule) ----------------
__device__ float g_E0[N_TOT * D];
__device__ float g_E1[N_TOT * D];
__device__ float g_all[N_TOT * 4 * D];
__device__ int   g_cnt[N_TOT];
__device__ int   g_rowptr[N_TOT + 1];
__device__ int   g_cur[N_TOT];
__device__ int   g_bsum[SCAN_NBLK + 1];
__device__ int2  g_csr[NNZ];
// Pre-packed W fragments: [layer][ntile(8)][ks(8)][lane(32)] = {bh0,bh1,bl0,bl1}
__device__ uint4 g_Wfrag[N_LAYERS * 8 * 8 * 32];

// ---------------------------------------------------------------------------
__global__ void init_kernel(const float* __restrict__ user_emb,
                            const float* __restrict__ item_emb) {
    int i = blockIdx.x * blockDim.x + threadIdx.x;
    if (i >= N_TOT * D) return;
    float v = (i < N_USER * D) ? user_emb[i] : item_emb[i - N_USER * D];
    g_E0[i] = v;
    int row = i >> 6, col = i & 63;
    g_all[row * (4 * D) + col] = v;
    if (col == 0) g_cnt[row] = 0;
}

// ---------------------------------------------------------------------------
// Pre-pack W' = [Wgc; Wbi] (k-major 128 x 64) into per-lane MMA B-fragments,
// split-bf16 hi/lo. One block per layer; each thread packs 8 fragments.
// frag = { pack(hi[k0],hi[k0+1]), pack(hi[k0+8],hi[k0+9]),
//          pack(lo[k0],lo[k0+1]), pack(lo[k0+8],lo[k0+9]) }
// with n = ntile*8 + (lane>>2), k0 = ks*16 + 2*(lane&3).
// ---------------------------------------------------------------------------
__device__ __forceinline__ uint32_t pack_hi(float a, float b) {
    __nv_bfloat162 h = __floats2bfloat162_rn(a, b);
    return *reinterpret_cast<uint32_t*>(&h);
}

__global__ void wfrag_kernel(const float* __restrict__ Wgc,
                             const float* __restrict__ Wbi) {
    int layer = blockIdx.x;
    const float* wg = Wgc + layer * 4096;
    const float* wb = Wbi + layer * 4096;
    for (int e = threadIdx.x; e < 2048; e += blockDim.x) {
        int ntile = e >> 8;
        int ks    = (e >> 5) & 7;
        int lane  = e & 31;
        int gid = lane >> 2, tig = lane & 3;
        int n  = ntile * 8 + gid;
        int k0 = ks * 16 + 2 * tig;

        float w[4];   // w'(k0), w'(k0+1), w'(k0+8), w'(k0+9) at column n
        int kk[4] = {k0, k0 + 1, k0 + 8, k0 + 9};
        #pragma unroll
        for (int q = 0; q < 4; q++) {
            int k = kk[q];
            w[q] = (k < 64) ? wg[k * 64 + n] : wb[(k - 64) * 64 + n];
        }
        float hi[4], lo[4];
        #pragma unroll
        for (int q = 0; q < 4; q++) {
            __nv_bfloat16 h = __float2bfloat16(w[q]);
            hi[q] = __bfloat162float(h);
            lo[q] = w[q] - hi[q];
        }
        uint4 f;
        f.x = pack_hi(hi[0], hi[1]);
        f.y = pack_hi(hi[2], hi[3]);
        f.z = pack_hi(lo[0], lo[1]);
        f.w = pack_hi(lo[2], lo[3]);
        g_Wfrag[(layer * 8 + ntile) * 256 + ks * 32 + lane] = f;
    }
}

// ---------------------------------------------------------------------------
// CSR build
// ---------------------------------------------------------------------------
__global__ void hist_kernel(const int* __restrict__ rows) {
    int i = blockIdx.x * blockDim.x + threadIdx.x;
    if (i < NNZ) atomicAdd(&g_cnt[rows[i]], 1);
}

__global__ void scan1_kernel() {
    __shared__ int s[SCAN_B];
    int tid = threadIdx.x;
    int gid = blockIdx.x * SCAN_B + tid;
    int v = (gid < N_TOT) ? g_cnt[gid] : 0;
    s[tid] = v;
    __syncthreads();
    #pragma unroll
    for (int off = 1; off < SCAN_B; off <<= 1) {
        int t = (tid >= off) ? s[tid - off] : 0;
        __syncthreads();
        s[tid] += t;
        __syncthreads();
    }
    if (gid < N_TOT) g_rowptr[gid] = s[tid] - v;
    if (tid == SCAN_B - 1) g_bsum[blockIdx.x] = s[tid];
}

__global__ void scan2_kernel() {
    __shared__ int s[256];
    int tid = threadIdx.x;
    int v = (tid < SCAN_NBLK) ? g_bsum[tid] : 0;
    s[tid] = v;
    __syncthreads();
    #pragma unroll
    for (int off = 1; off < 256; off <<= 1) {
        int t = (tid >= off) ? s[tid - off] : 0;
        __syncthreads();
        s[tid] += t;
        __syncthreads();
    }
    if (tid < SCAN_NBLK) g_bsum[tid] = s[tid] - v;
}

__global__ void scan3_kernel() {
    int gid = blockIdx.x * SCAN_B + threadIdx.x;
    if (gid < N_TOT) {
        g_rowptr[gid] += g_bsum[blockIdx.x];
        g_cur[gid] = 0;
    }
    if (gid == 0) g_rowptr[N_TOT] = NNZ;
}

__global__ void scatter_kernel(const float* __restrict__ vals,
                               const int*   __restrict__ rows,
                               const int*   __restrict__ cols) {
    int i = blockIdx.x * blockDim.x + threadIdx.x;
    if (i >= NNZ) return;
    int r = rows[i];
    int pos = g_rowptr[r] + atomicAdd(&g_cur[r], 1);
    g_csr[pos] = make_int2(cols[i], __float_as_int(vals[i]));
}

// ---------------------------------------------------------------------------
#define MMA_BF16(C, A0, A1, A2, A3, B0, B1)                                   \
    asm volatile(                                                             \
        "mma.sync.aligned.m16n8k16.row.col.f32.bf16.bf16.f32 "                \
        "{%0,%1,%2,%3}, {%4,%5,%6,%7}, {%8,%9}, {%0,%1,%2,%3};"               \
        : "+f"(C[0]), "+f"(C[1]), "+f"(C[2]), "+f"(C[3])                      \
        : "r"(A0), "r"(A1), "r"(A2), "r"(A3), "r"(B0), "r"(B1))

// ---------------------------------------------------------------------------
// FUSED layer kernel (R6 structure; B via pre-packed coalesced fragments):
//   Phase 1: CSR SPMM (256 threads, 16/row) -> sA = [L+E | L*E] bf16 hi/lo
//   Phase 2: mma.sync GEMM (hi*hi + hi*lo + lo*hi); B frags: 1 LDG.128/(t,ks)
//   Phase 3: epilogue (+2b, leaky-relu, row-norm, stores)
// ---------------------------------------------------------------------------
__global__ void __launch_bounds__(256)
fused_layer_kernel(const float* __restrict__ ego_in,
                   float*       __restrict__ ego_out,
                   const uint4* __restrict__ Wfrag,
                   const float* __restrict__ bb,
                   int layer) {
    __shared__ __nv_bfloat16 sAhi[32 * SAP];
    __shared__ __nv_bfloat16 sAlo[32 * SAP];
    __shared__ float sC[32 * 64];

    int tid = threadIdx.x;
    int rowBase = blockIdx.x * ROWS_PER_BLK;

    // ---- Phase 1: CSR SPMM, 16 threads/row, 2 passes over 32 rows ----
    {
        int rsub = tid >> 4;            // 0..15
        int c    = (tid & 15) << 2;     // float4 column offset
        #pragma unroll
        for (int pass = 0; pass < 2; pass++) {
            int rl  = pass * 16 + rsub;        // 0..31
            int row = rowBase + rl;
            float4 acc = make_float4(0.f, 0.f, 0.f, 0.f);
            float4 e   = make_float4(0.f, 0.f, 0.f, 0.f);
            if (row < N_TOT) {
                int s0 = g_rowptr[row];
                int e0 = g_rowptr[row + 1];
                int j = s0;
                for (; j + 4 <= e0; j += 4) {
                    int2 a  = g_csr[j];
                    int2 b  = g_csr[j + 1];
                    int2 cc = g_csr[j + 2];
                    int2 dd = g_csr[j + 3];
                    float4 va = __ldg((const float4*)&ego_in[a.x * D + c]);
                    float4 vb = __ldg((const float4*)&ego_in[b.x * D + c]);
                    float4 vc = __ldg((const float4*)&ego_in[cc.x * D + c]);
                    float4 vd = __ldg((const float4*)&ego_in[dd.x * D + c]);
                    float fa = __int_as_float(a.y);
                    float fb = __int_as_float(b.y);
                    float fc = __int_as_float(cc.y);
                    float fd = __int_as_float(dd.y);
                    acc.x += fa * va.x + fb * vb.x + fc * vc.x + fd * vd.x;
                    acc.y += fa * va.y + fb * vb.y + fc * vc.y + fd * vd.y;
                    acc.z += fa * va.z + fb * vb.z + fc * vc.z + fd * vd.z;
                    acc.w += fa * va.w + fb * vb.w + fc * vc.w + fd * vd.w;
                }
                for (; j < e0; j++) {
                    int2 a = g_csr[j];
                    float4 va = __ldg((const float4*)&ego_in[a.x * D + c]);
                    float fa = __int_as_float(a.y);
                    acc.x += fa * va.x; acc.y += fa * va.y;
                    acc.z += fa * va.z; acc.w += fa * va.w;
                }
                e = *(const float4*)&ego_in[row * D + c];
            }
            float li[4] = {acc.x + e.x, acc.y + e.y, acc.z + e.z, acc.w + e.w};
            float bi[4] = {acc.x * e.x, acc.y * e.y, acc.z * e.z, acc.w * e.w};

            uint32_t h0 = pack_hi(li[0], li[1]);
            uint32_t h1 = pack_hi(li[2], li[3]);
            __nv_bfloat162 hh0 = *reinterpret_cast<__nv_bfloat162*>(&h0);
            __nv_bfloat162 hh1 = *reinterpret_cast<__nv_bfloat162*>(&h1);
            uint32_t l0 = pack_hi(li[0] - __bfloat162float(hh0.x),
                                  li[1] - __bfloat162float(hh0.y));
            uint32_t l1 = pack_hi(li[2] - __bfloat162float(hh1.x),
                                  li[3] - __bfloat162float(hh1.y));
            uint32_t h2 = pack_hi(bi[0], bi[1]);
            uint32_t h3 = pack_hi(bi[2], bi[3]);
            __nv_bfloat162 hh2 = *reinterpret_cast<__nv_bfloat162*>(&h2);
            __nv_bfloat162 hh3 = *reinterpret_cast<__nv_bfloat162*>(&h3);
            uint32_t l2 = pack_hi(bi[0] - __bfloat162float(hh2.x),
                                  bi[1] - __bfloat162float(hh2.y));
            uint32_t l3 = pack_hi(bi[2] - __bfloat162float(hh3.x),
                                  bi[3] - __bfloat162float(hh3.y));

            *(uint2*)&sAhi[rl * SAP + c]      = make_uint2(h0, h1);
            *(uint2*)&sAlo[rl * SAP + c]      = make_uint2(l0, l1);
            *(uint2*)&sAhi[rl * SAP + 64 + c] = make_uint2(h2, h3);
            *(uint2*)&sAlo[rl * SAP + 64 + c] = make_uint2(l2, l3);
        }
    }
    __syncthreads();

    // ---- Phase 2: tensor-core GEMM; B via coalesced pre-packed fragments ----
    int wid = tid >> 5, lane = tid & 31;
    int gid = lane >> 2, tig = lane & 3;
    int m = wid >> 2;                 // 0..1
    int nt0 = (wid & 3) * 2;          // n-tile pair

    float C0[4] = {0.f, 0.f, 0.f, 0.f};
    float C1[4] = {0.f, 0.f, 0.f, 0.f};

    // fragment base pointers for this warp's two n-tiles
    const uint4* fb0 = Wfrag + (nt0 * 256) + lane;
    const uint4* fb1 = Wfrag + ((nt0 + 1) * 256) + lane;

    int arow = m * 16 + gid;
    #pragma unroll
    for (int ks = 0; ks < 8; ks++) {
        int k0 = ks * 16 + 2 * tig;
        uint32_t ah0 = *(const uint32_t*)&sAhi[arow * SAP + k0];
        uint32_t ah1 = *(const uint32_t*)&sAhi[(arow + 8) * SAP + k0];
        uint32_t ah2 = *(const uint32_t*)&sAhi[arow * SAP + k0 + 8];
        uint32_t ah3 = *(const uint32_t*)&sAhi[(arow + 8) * SAP + k0 + 8];
        uint32_t al0 = *(const uint32_t*)&sAlo[arow * SAP + k0];
        uint32_t al1 = *(const uint32_t*)&sAlo[(arow + 8) * SAP + k0];
        uint32_t al2 = *(const uint32_t*)&sAlo[arow * SAP + k0 + 8];
        uint32_t al3 = *(const uint32_t*)&sAlo[(arow + 8) * SAP + k0 + 8];

        uint4 f0 = __ldg(fb0 + ks * 32);
        uint4 f1 = __ldg(fb1 + ks * 32);

        MMA_BF16(C0, ah0, ah1, ah2, ah3, f0.x, f0.y);   // hi*hi
        MMA_BF16(C0, ah0, ah1, ah2, ah3, f0.z, f0.w);   // hi*lo
        MMA_BF16(C0, al0, al1, al2, al3, f0.x, f0.y);   // lo*hi
        MMA_BF16(C1, ah0, ah1, ah2, ah3, f1.x, f1.y);
        MMA_BF16(C1, ah0, ah1, ah2, ah3, f1.z, f1.w);
        MMA_BF16(C1, al0, al1, al2, al3, f1.x, f1.y);
    }

    {
        int r = m * 16 + gid;
        #pragma unroll
        for (int t = 0; t < 2; t++) {
            const float* C = (t == 0) ? C0 : C1;
            int cb = (nt0 + t) * 8 + tig * 2;
            *(float2*)&sC[r * 64 + cb]       = make_float2(C[0], C[1]);
            *(float2*)&sC[(r + 8) * 64 + cb] = make_float2(C[2], C[3]);
        }
    }
    __syncthreads();

    // ---- Phase 3: epilogue (2 rows x 4 cols per thread) ----
    {
        int ty = tid >> 4;       // rows 2ty, 2ty+1
        int tx = tid & 15;       // cols 4tx..4tx+3
        float4 b4 = *(const float4*)&bb[4 * tx];
        float4 X = *(const float4*)&sC[(2 * ty) * 64 + 4 * tx];
        float4 Y = *(const float4*)&sC[(2 * ty + 1) * 64 + 4 * tx];

        // reference adds b_bi to BOTH branches -> 2*b
        float x0 = X.x + 2.f * b4.x, x1 = X.y + 2.f * b4.y;
        float x2 = X.z + 2.f * b4.z, x3 = X.w + 2.f * b4.w;
        float y0 = Y.x + 2.f * b4.x, y1 = Y.y + 2.f * b4.y;
        float y2 = Y.z + 2.f * b4.z, y3 = Y.w + 2.f * b4.w;

        x0 = x0 > 0.f ? x0 : 0.01f * x0;  x1 = x1 > 0.f ? x1 : 0.01f * x1;
        x2 = x2 > 0.f ? x2 : 0.01f * x2;  x3 = x3 > 0.f ? x3 : 0.01f * x3;
        y0 = y0 > 0.f ? y0 : 0.01f * y0;  y1 = y1 > 0.f ? y1 : 0.01f * y1;
        y2 = y2 > 0.f ? y2 : 0.01f * y2;  y3 = y3 > 0.f ? y3 : 0.01f * y3;

        float ss0 = x0 * x0 + x1 * x1 + x2 * x2 + x3 * x3;
        float ss1 = y0 * y0 + y1 * y1 + y2 * y2 + y3 * y3;
        #pragma unroll
        for (int o = 8; o; o >>= 1) {
            ss0 += __shfl_xor_sync(0xffffffffu, ss0, o);
            ss1 += __shfl_xor_sync(0xffffffffu, ss1, o);
        }
        float inv0 = 1.0f / fmaxf(sqrtf(ss0), 1e-12f);
        float inv1 = 1.0f / fmaxf(sqrtf(ss1), 1e-12f);

        int r0 = rowBase + 2 * ty;
        int r1 = r0 + 1;
        int co = (layer + 1) * D + 4 * tx;
        if (r0 < N_TOT) {
            *(float4*)&ego_out[r0 * D + 4 * tx] = make_float4(x0, x1, x2, x3);
            *(float4*)&g_all[r0 * (4 * D) + co] =
                make_float4(x0 * inv0, x1 * inv0, x2 * inv0, x3 * inv0);
        }
        if (r1 < N_TOT) {
            *(float4*)&ego_out[r1 * D + 4 * tx] = make_float4(y0, y1, y2, y3);
            *(float4*)&g_all[r1 * (4 * D) + co] =
                make_float4(y0 * inv1, y1 * inv1, y2 * inv1, y3 * inv1);
        }
    }
}

// ---------------------------------------------------------------------------
__global__ void gather_kernel(const int* __restrict__ users,
                              const int* __restrict__ pos_items,
                              const int* __restrict__ neg_items,
                              float* __restrict__ out) {
    int idx = blockIdx.x * blockDim.x + threadIdx.x;  // 3*B*256
    if (idx >= 3 * B_SZ * (4 * D)) return;
    int which = idx / (B_SZ * 4 * D);
    int rem   = idx - which * (B_SZ * 4 * D);
    int b = rem >> 8;
    int c = rem & 255;
    int row;
    if (which == 0)      row = users[b];
    else if (which == 1) row = N_USER + pos_items[b];
    else                 row = N_USER + neg_items[b];
    out[idx] = g_all[row * (4 * D) + c];
}

// ---------------------------------------------------------------------------
extern "C" void kernel_launch(void* const* d_in, const int* in_sizes, int n_in,
                              void* d_out, int out_size) {
    const float* user_emb  = (const float*)d_in[0];
    const float* item_emb  = (const float*)d_in[1];
    const float* W_gc      = (const float*)d_in[2];
    const float* W_bi      = (const float*)d_in[3];
    const float* b_bi      = (const float*)d_in[4];
    const float* vals      = (const float*)d_in[5];
    const int*   rows      = (const int*)d_in[6];
    const int*   cols      = (const int*)d_in[7];
    const int*   users     = (const int*)d_in[8];
    const int*   pos_items = (const int*)d_in[9];
    const int*   neg_items = (const int*)d_in[10];
    float* out = (float*)d_out;

    init_kernel<<<(N_TOT * D + 255) / 256, 256>>>(user_emb, item_emb);
    wfrag_kernel<<<N_LAYERS, 256>>>(W_gc, W_bi);

    hist_kernel<<<(NNZ + 255) / 256, 256>>>(rows);
    scan1_kernel<<<SCAN_NBLK, SCAN_B>>>();
    scan2_kernel<<<1, 256>>>();
    scan3_kernel<<<SCAN_NBLK, SCAN_B>>>();
    scatter_kernel<<<(NNZ + 255) / 256, 256>>>(vals, rows, cols);

    float* e0; float* e1;
    cudaGetSymbolAddress((void**)&e0, g_E0);
    cudaGetSymbolAddress((void**)&e1, g_E1);
    uint4* wfrag;
    cudaGetSymbolAddress((void**)&wfrag, g_Wfrag);

    for (int k = 0; k < N_LAYERS; k++) {
        const float* in   = (k & 1) ? e1 : e0;
        float*       outp = (k & 1) ? e0 : e1;
        fused_layer_kernel<<<LBLK, 256>>>(in, outp,
                                          wfrag + k * 8 * 256,
                                          b_bi + k * D, k);
    }

    gather_kernel<<<(3 * B_SZ * 4 * D + 255) / 256, 256>>>(users, pos_items,
                                                           neg_items, out);
}

// round 12
// speedup vs baseline: 1.8111x; 1.1938x over previous
#include <cuda_runtime.h>
#include <cuda_bf16.h>
#include <cuda_fp16.h>
#include <cstdint>

#define N_USER 50000
#define N_ITEM 100000
#define N_TOT  150000
#define D      64
#define NNZ    2400000
#define B_SZ   4096
#define N_LAYERS 3

#define SCAN_B 1024
#define SCAN_NBLK ((N_TOT + SCAN_B - 1) / SCAN_B)   // 147

#define ROWS_PER_BLK 32
#define LBLK ((N_TOT + ROWS_PER_BLK - 1) / ROWS_PER_BLK)  // 4688

#define SAP  136   // A-plane k-stride (bf16): bank-free frag loads
#define GSTR 192   // g_all row stride (3 slabs of 64)

// ---------------- device scratch (allocation-free rule) ----------------
__device__ uint32_t g_H0[N_TOT * 32];     // ego ping, half2 words (64 fp16/row)
__device__ uint32_t g_H1[N_TOT * 32];     // ego pong
__device__ float g_all[N_TOT * GSTR];     // [norm1 | norm2 | norm3]
__device__ int   g_cnt[N_TOT];
__device__ int   g_rowptr[N_TOT + 1];
__device__ int   g_cur[N_TOT];
__device__ int   g_bsum[SCAN_NBLK + 1];
__device__ int2  g_csr[NNZ];
// Pre-packed W fragments: [layer][ntile(8)][ks(8)][lane(32)] = {bh0,bh1,bl0,bl1}
__device__ uint4 g_Wfrag[N_LAYERS * 8 * 8 * 32];

// ---------------------------------------------------------------------------
// init: ego(fp16) = concat(user,item); zero g_cnt
// ---------------------------------------------------------------------------
__global__ void init_kernel(const float* __restrict__ user_emb,
                            const float* __restrict__ item_emb) {
    int i = blockIdx.x * blockDim.x + threadIdx.x;   // half2 word index
    if (i >= N_TOT * 32) return;
    int e0 = i * 2;                                  // element index
    float2 v;
    if (e0 < N_USER * D) v = *(const float2*)&user_emb[e0];
    else                 v = *(const float2*)&item_emb[e0 - N_USER * D];
    __half2 h = __floats2half2_rn(v.x, v.y);
    g_H0[i] = *reinterpret_cast<uint32_t*>(&h);
    if (i < N_TOT) g_cnt[i] = 0;
}

// ---------------------------------------------------------------------------
__device__ __forceinline__ uint32_t pack_hi(float a, float b) {
    __nv_bfloat162 h = __floats2bfloat162_rn(a, b);
    return *reinterpret_cast<uint32_t*>(&h);
}

__global__ void wfrag_kernel(const float* __restrict__ Wgc,
                             const float* __restrict__ Wbi) {
    int layer = blockIdx.x;
    const float* wg = Wgc + layer * 4096;
    const float* wb = Wbi + layer * 4096;
    for (int e = threadIdx.x; e < 2048; e += blockDim.x) {
        int ntile = e >> 8;
        int ks    = (e >> 5) & 7;
        int lane  = e & 31;
        int gid = lane >> 2, tig = lane & 3;
        int n  = ntile * 8 + gid;
        int k0 = ks * 16 + 2 * tig;

        float w[4];
        int kk[4] = {k0, k0 + 1, k0 + 8, k0 + 9};
        #pragma unroll
        for (int q = 0; q < 4; q++) {
            int k = kk[q];
            w[q] = (k < 64) ? wg[k * 64 + n] : wb[(k - 64) * 64 + n];
        }
        float hi[4], lo[4];
        #pragma unroll
        for (int q = 0; q < 4; q++) {
            __nv_bfloat16 h = __float2bfloat16(w[q]);
            hi[q] = __bfloat162float(h);
            lo[q] = w[q] - hi[q];
        }
        uint4 f;
        f.x = pack_hi(hi[0], hi[1]);
        f.y = pack_hi(hi[2], hi[3]);
        f.z = pack_hi(lo[0], lo[1]);
        f.w = pack_hi(lo[2], lo[3]);
        g_Wfrag[(layer * 8 + ntile) * 256 + ks * 32 + lane] = f;
    }
}

// ---------------------------------------------------------------------------
// CSR build
// ---------------------------------------------------------------------------
__global__ void hist_kernel(const int* __restrict__ rows) {
    int i = blockIdx.x * blockDim.x + threadIdx.x;
    if (i < NNZ) atomicAdd(&g_cnt[rows[i]], 1);
}

__global__ void scan1_kernel() {
    __shared__ int s[SCAN_B];
    int tid = threadIdx.x;
    int gid = blockIdx.x * SCAN_B + tid;
    int v = (gid < N_TOT) ? g_cnt[gid] : 0;
    s[tid] = v;
    __syncthreads();
    #pragma unroll
    for (int off = 1; off < SCAN_B; off <<= 1) {
        int t = (tid >= off) ? s[tid - off] : 0;
        __syncthreads();
        s[tid] += t;
        __syncthreads();
    }
    if (gid < N_TOT) g_rowptr[gid] = s[tid] - v;
    if (tid == SCAN_B - 1) g_bsum[blockIdx.x] = s[tid];
}

__global__ void scan2_kernel() {
    __shared__ int s[256];
    int tid = threadIdx.x;
    int v = (tid < SCAN_NBLK) ? g_bsum[tid] : 0;
    s[tid] = v;
    __syncthreads();
    #pragma unroll
    for (int off = 1; off < 256; off <<= 1) {
        int t = (tid >= off) ? s[tid - off] : 0;
        __syncthreads();
        s[tid] += t;
        __syncthreads();
    }
    if (tid < SCAN_NBLK) g_bsum[tid] = s[tid] - v;
}

__global__ void scan3_kernel() {
    int gid = blockIdx.x * SCAN_B + threadIdx.x;
    if (gid < N_TOT) {
        g_rowptr[gid] += g_bsum[blockIdx.x];
        g_cur[gid] = 0;
    }
    if (gid == 0) g_rowptr[N_TOT] = NNZ;
}

__global__ void scatter_kernel(const float* __restrict__ vals,
                               const int*   __restrict__ rows,
                               const int*   __restrict__ cols) {
    int i = blockIdx.x * blockDim.x + threadIdx.x;
    if (i >= NNZ) return;
    int r = rows[i];
    int pos = g_rowptr[r] + atomicAdd(&g_cur[r], 1);
    g_csr[pos] = make_int2(cols[i], __float_as_int(vals[i]));
}

// ---------------------------------------------------------------------------
#define MMA_BF16(C, A0, A1, A2, A3, B0, B1)                                   \
    asm volatile(                                                             \
        "mma.sync.aligned.m16n8k16.row.col.f32.bf16.bf16.f32 "                \
        "{%0,%1,%2,%3}, {%4,%5,%6,%7}, {%8,%9}, {%0,%1,%2,%3};"               \
        : "+f"(C[0]), "+f"(C[1]), "+f"(C[2]), "+f"(C[3])                      \
        : "r"(A0), "r"(A1), "r"(A2), "r"(A3), "r"(B0), "r"(B1))

__device__ __forceinline__ float4 cvt_h4(uint2 hv) {
    float2 a = __half22float2(*reinterpret_cast<__half2*>(&hv.x));
    float2 b = __half22float2(*reinterpret_cast<__half2*>(&hv.y));
    return make_float4(a.x, a.y, b.x, b.y);
}

// ---------------------------------------------------------------------------
// FUSED layer kernel (fp16 gather; pre-packed B fragments):
//   Phase 1: CSR SPMM (16 thr/row, fp16 in, fp32 acc) -> sA bf16 hi/lo planes
//   Phase 2: mma.sync GEMM (hi*hi + hi*lo + lo*hi); B: 1 LDG.128/(t,ks)
//   Phase 3: epilogue (+2b, leaky-relu, row-norm, fp16 ego_out + g_all)
// ---------------------------------------------------------------------------
__global__ void __launch_bounds__(256)
fused_layer_kernel(const uint32_t* __restrict__ egoH_in,
                   uint32_t*       __restrict__ egoH_out,
                   const uint4* __restrict__ Wfrag,
                   const float* __restrict__ bb,
                   int layer) {
    __shared__ __nv_bfloat16 sAhi[32 * SAP];
    __shared__ __nv_bfloat16 sAlo[32 * SAP];
    __shared__ float sC[32 * 64];

    int tid = threadIdx.x;
    int rowBase = blockIdx.x * ROWS_PER_BLK;

    // ---- Phase 1: CSR SPMM, 16 threads/row, 2 passes over 32 rows ----
    {
        int rsub = tid >> 4;            // 0..15
        int cg   = tid & 15;            // column group
        int c    = cg << 2;             // element offset
        int w2   = cg << 1;             // half2-word offset
        #pragma unroll
        for (int pass = 0; pass < 2; pass++) {
            int rl  = pass * 16 + rsub;        // 0..31
            int row = rowBase + rl;
            float4 acc = make_float4(0.f, 0.f, 0.f, 0.f);
            float4 e   = make_float4(0.f, 0.f, 0.f, 0.f);
            if (row < N_TOT) {
                int s0 = g_rowptr[row];
                int e0 = g_rowptr[row + 1];
                int j = s0;
                for (; j + 4 <= e0; j += 4) {
                    int2 a  = g_csr[j];
                    int2 b  = g_csr[j + 1];
                    int2 cc = g_csr[j + 2];
                    int2 dd = g_csr[j + 3];
                    uint2 ha = __ldg((const uint2*)&egoH_in[a.x * 32 + w2]);
                    uint2 hb = __ldg((const uint2*)&egoH_in[b.x * 32 + w2]);
                    uint2 hc = __ldg((const uint2*)&egoH_in[cc.x * 32 + w2]);
                    uint2 hd = __ldg((const uint2*)&egoH_in[dd.x * 32 + w2]);
                    float4 va = cvt_h4(ha);
                    float4 vb = cvt_h4(hb);
                    float4 vc = cvt_h4(hc);
                    float4 vd = cvt_h4(hd);
                    float fa = __int_as_float(a.y);
                    float fb = __int_as_float(b.y);
                    float fc = __int_as_float(cc.y);
                    float fd = __int_as_float(dd.y);
                    acc.x += fa * va.x + fb * vb.x + fc * vc.x + fd * vd.x;
                    acc.y += fa * va.y + fb * vb.y + fc * vc.y + fd * vd.y;
                    acc.z += fa * va.z + fb * vb.z + fc * vc.z + fd * vd.z;
                    acc.w += fa * va.w + fb * vb.w + fc * vc.w + fd * vd.w;
                }
                for (; j < e0; j++) {
                    int2 a = g_csr[j];
                    float4 va = cvt_h4(__ldg((const uint2*)&egoH_in[a.x * 32 + w2]));
                    float fa = __int_as_float(a.y);
                    acc.x += fa * va.x; acc.y += fa * va.y;
                    acc.z += fa * va.z; acc.w += fa * va.w;
                }
                e = cvt_h4(__ldg((const uint2*)&egoH_in[row * 32 + w2]));
            }
            float li[4] = {acc.x + e.x, acc.y + e.y, acc.z + e.z, acc.w + e.w};
            float bi[4] = {acc.x * e.x, acc.y * e.y, acc.z * e.z, acc.w * e.w};

            uint32_t h0 = pack_hi(li[0], li[1]);
            uint32_t h1 = pack_hi(li[2], li[3]);
            __nv_bfloat162 hh0 = *reinterpret_cast<__nv_bfloat162*>(&h0);
            __nv_bfloat162 hh1 = *reinterpret_cast<__nv_bfloat162*>(&h1);
            uint32_t l0 = pack_hi(li[0] - __bfloat162float(hh0.x),
                                  li[1] - __bfloat162float(hh0.y));
            uint32_t l1 = pack_hi(li[2] - __bfloat162float(hh1.x),
                                  li[3] - __bfloat162float(hh1.y));
            uint32_t h2 = pack_hi(bi[0], bi[1]);
            uint32_t h3 = pack_hi(bi[2], bi[3]);
            __nv_bfloat162 hh2 = *reinterpret_cast<__nv_bfloat162*>(&h2);
            __nv_bfloat162 hh3 = *reinterpret_cast<__nv_bfloat162*>(&h3);
            uint32_t l2 = pack_hi(bi[0] - __bfloat162float(hh2.x),
                                  bi[1] - __bfloat162float(hh2.y));
            uint32_t l3 = pack_hi(bi[2] - __bfloat162float(hh3.x),
                                  bi[3] - __bfloat162float(hh3.y));

            *(uint2*)&sAhi[rl * SAP + c]      = make_uint2(h0, h1);
            *(uint2*)&sAlo[rl * SAP + c]      = make_uint2(l0, l1);
            *(uint2*)&sAhi[rl * SAP + 64 + c] = make_uint2(h2, h3);
            *(uint2*)&sAlo[rl * SAP + 64 + c] = make_uint2(l2, l3);
        }
    }
    __syncthreads();

    // ---- Phase 2: tensor-core GEMM; B via coalesced pre-packed fragments ----
    int wid = tid >> 5, lane = tid & 31;
    int gid = lane >> 2, tig = lane & 3;
    int m = wid >> 2;
    int nt0 = (wid & 3) * 2;

    float C0[4] = {0.f, 0.f, 0.f, 0.f};
    float C1[4] = {0.f, 0.f, 0.f, 0.f};

    const uint4* fb0 = Wfrag + (nt0 * 256) + lane;
    const uint4* fb1 = Wfrag + ((nt0 + 1) * 256) + lane;

    int arow = m * 16 + gid;
    #pragma unroll
    for (int ks = 0; ks < 8; ks++) {
        int k0 = ks * 16 + 2 * tig;
        uint32_t ah0 = *(const uint32_t*)&sAhi[arow * SAP + k0];
        uint32_t ah1 = *(const uint32_t*)&sAhi[(arow + 8) * SAP + k0];
        uint32_t ah2 = *(const uint32_t*)&sAhi[arow * SAP + k0 + 8];
        uint32_t ah3 = *(const uint32_t*)&sAhi[(arow + 8) * SAP + k0 + 8];
        uint32_t al0 = *(const uint32_t*)&sAlo[arow * SAP + k0];
        uint32_t al1 = *(const uint32_t*)&sAlo[(arow + 8) * SAP + k0];
        uint32_t al2 = *(const uint32_t*)&sAlo[arow * SAP + k0 + 8];
        uint32_t al3 = *(const uint32_t*)&sAlo[(arow + 8) * SAP + k0 + 8];

        uint4 f0 = __ldg(fb0 + ks * 32);
        uint4 f1 = __ldg(fb1 + ks * 32);

        MMA_BF16(C0, ah0, ah1, ah2, ah3, f0.x, f0.y);
        MMA_BF16(C0, ah0, ah1, ah2, ah3, f0.z, f0.w);
        MMA_BF16(C0, al0, al1, al2, al3, f0.x, f0.y);
        MMA_BF16(C1, ah0, ah1, ah2, ah3, f1.x, f1.y);
        MMA_BF16(C1, ah0, ah1, ah2, ah3, f1.z, f1.w);
        MMA_BF16(C1, al0, al1, al2, al3, f1.x, f1.y);
    }

    {
        int r = m * 16 + gid;
        #pragma unroll
        for (int t = 0; t < 2; t++) {
            const float* C = (t == 0) ? C0 : C1;
            int cb = (nt0 + t) * 8 + tig * 2;
            *(float2*)&sC[r * 64 + cb]       = make_float2(C[0], C[1]);
            *(float2*)&sC[(r + 8) * 64 + cb] = make_float2(C[2], C[3]);
        }
    }
    __syncthreads();

    // ---- Phase 3: epilogue (2 rows x 4 cols per thread) ----
    {
        int ty = tid >> 4;
        int tx = tid & 15;
        float4 b4 = *(const float4*)&bb[4 * tx];
        float4 X = *(const float4*)&sC[(2 * ty) * 64 + 4 * tx];
        float4 Y = *(const float4*)&sC[(2 * ty + 1) * 64 + 4 * tx];

        // reference adds b_bi to BOTH branches -> 2*b
        float x0 = X.x + 2.f * b4.x, x1 = X.y + 2.f * b4.y;
        float x2 = X.z + 2.f * b4.z, x3 = X.w + 2.f * b4.w;
        float y0 = Y.x + 2.f * b4.x, y1 = Y.y + 2.f * b4.y;
        float y2 = Y.z + 2.f * b4.z, y3 = Y.w + 2.f * b4.w;

        x0 = x0 > 0.f ? x0 : 0.01f * x0;  x1 = x1 > 0.f ? x1 : 0.01f * x1;
        x2 = x2 > 0.f ? x2 : 0.01f * x2;  x3 = x3 > 0.f ? x3 : 0.01f * x3;
        y0 = y0 > 0.f ? y0 : 0.01f * y0;  y1 = y1 > 0.f ? y1 : 0.01f * y1;
        y2 = y2 > 0.f ? y2 : 0.01f * y2;  y3 = y3 > 0.f ? y3 : 0.01f * y3;

        float ss0 = x0 * x0 + x1 * x1 + x2 * x2 + x3 * x3;
        float ss1 = y0 * y0 + y1 * y1 + y2 * y2 + y3 * y3;
        #pragma unroll
        for (int o = 8; o; o >>= 1) {
            ss0 += __shfl_xor_sync(0xffffffffu, ss0, o);
            ss1 += __shfl_xor_sync(0xffffffffu, ss1, o);
        }
        float inv0 = 1.0f / fmaxf(sqrtf(ss0), 1e-12f);
        float inv1 = 1.0f / fmaxf(sqrtf(ss1), 1e-12f);

        int r0 = rowBase + 2 * ty;
        int r1 = r0 + 1;
        int co = layer * D + 4 * tx;         // g_all has 3 slabs
        if (r0 < N_TOT) {
            __half2 p0 = __floats2half2_rn(x0, x1);
            __half2 p1 = __floats2half2_rn(x2, x3);
            uint2 pw = make_uint2(*reinterpret_cast<uint32_t*>(&p0),
                                  *reinterpret_cast<uint32_t*>(&p1));
            *(uint2*)&egoH_out[r0 * 32 + 2 * tx] = pw;
            *(float4*)&g_all[r0 * GSTR + co] =
                make_float4(x0 * inv0, x1 * inv0, x2 * inv0, x3 * inv0);
        }
        if (r1 < N_TOT) {
            __half2 p0 = __floats2half2_rn(y0, y1);
            __half2 p1 = __floats2half2_rn(y2, y3);
            uint2 pw = make_uint2(*reinterpret_cast<uint32_t*>(&p0),
                                  *reinterpret_cast<uint32_t*>(&p1));
            *(uint2*)&egoH_out[r1 * 32 + 2 * tx] = pw;
            *(float4*)&g_all[r1 * GSTR + co] =
                make_float4(y0 * inv1, y1 * inv1, y2 * inv1, y3 * inv1);
        }
    }
}

// ---------------------------------------------------------------------------
// Final gather: col 0-63 straight from emb inputs; 64-255 from g_all slabs
// ---------------------------------------------------------------------------
__global__ void gather_kernel(const int* __restrict__ users,
                              const int* __restrict__ pos_items,
                              const int* __restrict__ neg_items,
                              const float* __restrict__ user_emb,
                              const float* __restrict__ item_emb,
                              float* __restrict__ out) {
    int idx = blockIdx.x * blockDim.x + threadIdx.x;  // 3*B*256
    if (idx >= 3 * B_SZ * 256) return;
    int which = idx / (B_SZ * 256);
    int rem   = idx - which * (B_SZ * 256);
    int b = rem >> 8;
    int c = rem & 255;
    int row; const float* emb;
    if (which == 0)      { row = users[b];     emb = user_emb; }
    else if (which == 1) { row = pos_items[b]; emb = item_emb; }
    else                 { row = neg_items[b]; emb = item_emb; }
    float v;
    if (c < 64) {
        v = emb[row * 64 + c];
    } else {
        int grow = (which == 0) ? row : (N_USER + row);
        v = g_all[grow * GSTR + (c - 64)];
    }
    out[idx] = v;
}

// ---------------------------------------------------------------------------
extern "C" void kernel_launch(void* const* d_in, const int* in_sizes, int n_in,
                              void* d_out, int out_size) {
    const float* user_emb  = (const float*)d_in[0];
    const float* item_emb  = (const float*)d_in[1];
    const float* W_gc      = (const float*)d_in[2];
    const float* W_bi      = (const float*)d_in[3];
    const float* b_bi      = (const float*)d_in[4];
    const float* vals      = (const float*)d_in[5];
    const int*   rows      = (const int*)d_in[6];
    const int*   cols      = (const int*)d_in[7];
    const int*   users     = (const int*)d_in[8];
    const int*   pos_items = (const int*)d_in[9];
    const int*   neg_items = (const int*)d_in[10];
    float* out = (float*)d_out;

    init_kernel<<<(N_TOT * 32 + 255) / 256, 256>>>(user_emb, item_emb);
    wfrag_kernel<<<N_LAYERS, 256>>>(W_gc, W_bi);

    hist_kernel<<<(NNZ + 255) / 256, 256>>>(rows);
    scan1_kernel<<<SCAN_NBLK, SCAN_B>>>();
    scan2_kernel<<<1, 256>>>();
    scan3_kernel<<<SCAN_NBLK, SCAN_B>>>();
    scatter_kernel<<<(NNZ + 255) / 256, 256>>>(vals, rows, cols);

    uint32_t* h0; uint32_t* h1;
    cudaGetSymbolAddress((void**)&h0, g_H0);
    cudaGetSymbolAddress((void**)&h1, g_H1);
    uint4* wfrag;
    cudaGetSymbolAddress((void**)&wfrag, g_Wfrag);

    for (int k = 0; k < N_LAYERS; k++) {
        const uint32_t* in   = (k & 1) ? h1 : h0;
        uint32_t*       outp = (k & 1) ? h0 : h1;
        fused_layer_kernel<<<LBLK, 256>>>(in, outp,
                                          wfrag + k * 8 * 256,
                                          b_bi + k * D, k);
    }

    gather_kernel<<<(3 * B_SZ * 256 + 255) / 256, 256>>>(
        users, pos_items, neg_items, user_emb, item_emb, out);
}